// round 1
// baseline (speedup 1.0000x reference)
#include <cuda_runtime.h>
#include <cuda_bf16.h>
#include <cstdint>

// Problem shape
#define BB      16
#define TT      4096
#define UU      1024
#define TC      16                 // t-rows per chunk (held in registers)
#define NC      (TT / TC)          // 256 chunks per batch chain
#define U4      (UU / 4)           // 256 float4 per row
#define THREADS 256                // one thread per float4 column
#define FACTOR  0.5f

// Decoupled-lookback scratch (device globals: no allocation allowed).
// g_agg / g_inc: per-(b,chunk) aggregate / inclusive-prefix vectors (1024 floats each).
__device__ float4 g_agg[BB * NC * U4];          // 16 MiB
__device__ float4 g_inc[BB * NC * U4];          // 16 MiB
// Flags: 0 = invalid, 1 = aggregate ready, 2 = inclusive ready.
// Last slot doubles as the dynamic-ticket counter. Reset by memset each launch.
__device__ unsigned int g_flags[BB * NC + 1];

__device__ __forceinline__ void st_release_gpu(unsigned int* p, unsigned int v) {
    asm volatile("st.release.gpu.u32 [%0], %1;" :: "l"(p), "r"(v) : "memory");
}
__device__ __forceinline__ unsigned int ld_acquire_gpu(unsigned int* p) {
    unsigned int v;
    asm volatile("ld.acquire.gpu.u32 %0, [%1];" : "=r"(v) : "l"(p) : "memory");
    return v;
}

__global__ __launch_bounds__(THREADS)
void rac_scan_kernel(const float4* __restrict__ xv,
                     const float4* __restrict__ h0v,
                     float4* __restrict__ outv) {
    __shared__ unsigned int s_vb;
    __shared__ unsigned int s_f;

    const int tid = threadIdx.x;

    // Dynamic ticket: guarantees chain order == scheduling order (no deadlock).
    if (tid == 0) s_vb = atomicAdd(&g_flags[BB * NC], 1u);
    __syncthreads();
    const unsigned int vb = s_vb;
    const int b = vb & (BB - 1);   // batch iterates fastest -> all 16 chains advance together
    const int c = vb >> 4;         // chunk index along the chain

    // ---- Load this block's 16 x 1024 chunk; each thread owns one float4 column ----
    const size_t base = ((size_t)b * TT + (size_t)c * TC) * U4 + tid;
    float4 v[TC];
#pragma unroll
    for (int t = 0; t < TC; t++) v[t] = xv[base + (size_t)t * U4];

    // In-register inclusive prefix over the 16 rows (4 independent FADD chains).
#pragma unroll
    for (int t = 1; t < TC; t++) {
        v[t].x += v[t - 1].x;
        v[t].y += v[t - 1].y;
        v[t].z += v[t - 1].z;
        v[t].w += v[t - 1].w;
    }
    const float4 agg = v[TC - 1];

    const int sidx = (b * NC + c) * U4 + tid;
    float4 excl = make_float4(0.f, 0.f, 0.f, 0.f);

    if (c == 0) {
        // Chain head: inclusive == aggregate, publish directly as PREFIX_READY.
        g_inc[sidx] = agg;
        __threadfence();
        __syncthreads();
        if (tid == 0) st_release_gpu(&g_flags[b * NC + 0], 2u);
    } else {
        // Publish aggregate first so successors can make progress immediately.
        g_agg[sidx] = agg;
        __threadfence();
        __syncthreads();
        if (tid == 0) st_release_gpu(&g_flags[b * NC + c], 1u);

        // Decoupled lookback: walk predecessors until an inclusive prefix is found.
        int p = c - 1;
        for (;;) {
            if (tid == 0) {
                unsigned int f;
                do { f = ld_acquire_gpu(&g_flags[b * NC + p]); } while (f == 0u);
                s_f = f;
            }
            __syncthreads();
            const unsigned int f = s_f;
            const int pidx = (b * NC + p) * U4 + tid;
            const float4 a = (f == 2u) ? __ldcg(&g_inc[pidx]) : __ldcg(&g_agg[pidx]);
            excl.x += a.x; excl.y += a.y; excl.z += a.z; excl.w += a.w;
            __syncthreads();          // protect s_f before next poll
            if (f == 2u) break;
            p--;
        }

        // Publish our inclusive prefix (upgrade flag 1 -> 2).
        float4 inc;
        inc.x = excl.x + agg.x; inc.y = excl.y + agg.y;
        inc.z = excl.z + agg.z; inc.w = excl.w + agg.w;
        g_inc[sidx] = inc;
        __threadfence();
        __syncthreads();
        if (tid == 0) st_release_gpu(&g_flags[b * NC + c], 2u);
    }

    // ---- Epilogue: out = h0 + FACTOR * (exclusive + local_prefix) ----
    const float4 h = h0v[b * U4 + tid];
#pragma unroll
    for (int t = 0; t < TC; t++) {
        float4 o;
        o.x = h.x + FACTOR * (excl.x + v[t].x);
        o.y = h.y + FACTOR * (excl.y + v[t].y);
        o.z = h.z + FACTOR * (excl.z + v[t].z);
        o.w = h.w + FACTOR * (excl.w + v[t].w);
        outv[base + (size_t)t * U4] = o;
    }
}

extern "C" void kernel_launch(void* const* d_in, const int* in_sizes, int n_in,
                              void* d_out, int out_size) {
    (void)in_sizes; (void)n_in; (void)out_size;
    const float4* xv  = (const float4*)d_in[0];   // x:  (16, 4096, 1024) f32
    const float4* h0v = (const float4*)d_in[1];   // h0: (16, 1024) f32
    float4* outv      = (float4*)d_out;           // out:(16, 4096, 1024) f32

    // Reset flags + ticket every launch (captured as a memset node).
    void* flags_ptr = nullptr;
    cudaGetSymbolAddress(&flags_ptr, g_flags);
    cudaMemsetAsync(flags_ptr, 0, (BB * NC + 1) * sizeof(unsigned int), 0);

    rac_scan_kernel<<<BB * NC, THREADS>>>(xv, h0v, outv);
}

// round 2
// speedup vs baseline: 1.1889x; 1.1889x over previous
#include <cuda_runtime.h>
#include <cuda_bf16.h>
#include <cstdint>

// Problem shape
#define BB      16
#define TT      4096
#define UU      1024
#define TC      16                 // t-rows per chunk (held in registers)
#define NC      (TT / TC)          // 256 chunks per batch chain
#define U4      (UU / 4)           // 256 float4 per row
#define THREADS 256                // one thread per float4 column
#define FACTOR  0.5f

// Decoupled-lookback scratch (device globals: no allocation allowed).
__device__ float4 g_agg[BB * NC * U4];          // 16 MiB
__device__ float4 g_inc[BB * NC * U4];          // 16 MiB
// Flags: 0 = invalid, 1 = aggregate ready, 2 = inclusive ready.
// Last slot doubles as the dynamic-ticket counter. Reset by memset each launch.
__device__ unsigned int g_flags[BB * NC + 1];

__device__ __forceinline__ void st_release_gpu(unsigned int* p, unsigned int v) {
    asm volatile("st.release.gpu.u32 [%0], %1;" :: "l"(p), "r"(v) : "memory");
}
__device__ __forceinline__ unsigned int ld_acquire_gpu(const unsigned int* p) {
    unsigned int v;
    asm volatile("ld.acquire.gpu.u32 %0, [%1];" : "=r"(v) : "l"(p) : "memory");
    return v;
}

__global__ __launch_bounds__(THREADS)
void rac_scan_kernel(const float4* __restrict__ xv,
                     const float4* __restrict__ h0v,
                     float4* __restrict__ outv) {
    __shared__ unsigned int s_vb;
    __shared__ int s_D;        // aggregates to consume this round
    __shared__ int s_done;     // 1 => inclusive found at distance s_D

    const int tid = threadIdx.x;

    // Dynamic ticket: chain order == scheduling order (no deadlock).
    if (tid == 0) s_vb = atomicAdd(&g_flags[BB * NC], 1u);
    __syncthreads();
    const unsigned int vb = s_vb;
    const int b = vb & (BB - 1);   // batch fastest -> all 16 chains advance together
    const int c = vb >> 4;         // chunk index along the chain

    // ---- Load this block's 16 x 1024 chunk; one float4 column per thread ----
    const size_t base = ((size_t)b * TT + (size_t)c * TC) * U4 + tid;
    const float4 h = h0v[b * U4 + tid];
    float4 v[TC];
#pragma unroll
    for (int t = 0; t < TC; t++) v[t] = xv[base + (size_t)t * U4];

    // In-register inclusive prefix over the 16 rows (4 independent FADD chains).
#pragma unroll
    for (int t = 1; t < TC; t++) {
        v[t].x += v[t - 1].x;
        v[t].y += v[t - 1].y;
        v[t].z += v[t - 1].z;
        v[t].w += v[t - 1].w;
    }
    const float4 agg = v[TC - 1];

    const int chain = b * NC;            // flag base for this chain
    const int sidx  = (chain + c) * U4 + tid;
    const bool is_last = (c == NC - 1);  // no successor: skip publishes
    float4 excl = make_float4(0.f, 0.f, 0.f, 0.f);

    if (c == 0) {
        if (!is_last) {
            g_inc[sidx] = agg;
            __threadfence();
            __syncthreads();
            if (tid == 0) st_release_gpu(&g_flags[chain], 2u);
        }
    } else {
        // Publish aggregate so successors can make progress immediately.
        g_agg[sidx] = agg;
        __threadfence();
        __syncthreads();
        if (tid == 0) st_release_gpu(&g_flags[chain + c], 1u);

        // ---- Parallelized (windowed) lookback ----
        // Warp 0 polls 32 predecessor flags at once; all 256 threads then
        // consume D aggregates with independent (MLP) loads.
        int base_p = c - 1;
        for (;;) {
            if (tid < 32) {
                const int p = base_p - tid;
                const unsigned f = (p >= 0) ? ld_acquire_gpu(&g_flags[chain + p]) : 0u;
                const unsigned b1 = __ballot_sync(0xffffffffu, f >= 1u);
                const unsigned b2 = __ballot_sync(0xffffffffu, f == 2u);
                if (tid == 0) {
                    const int k = __ffs(~b1);                 // first not-ready lane (+1); 0 => all 32 ready
                    const int nready = (k == 0) ? 32 : (k - 1);
                    const int l2 = __ffs(b2) - 1;             // nearest inclusive; -1 if none
                    if (l2 >= 0 && l2 <= nready) { s_done = 1; s_D = l2; }
                    else                         { s_done = 0; s_D = nready; }
                }
            }
            __syncthreads();
            const int D = s_D;
            const int done = s_done;
            // D independent aggregate loads -> one L2 round-trip, not D.
            for (int l = 0; l < D; l++) {
                const float4 a = __ldcg(&g_agg[(chain + base_p - l) * U4 + tid]);
                excl.x += a.x; excl.y += a.y; excl.z += a.z; excl.w += a.w;
            }
            if (done) {
                const float4 a = __ldcg(&g_inc[(chain + base_p - D) * U4 + tid]);
                excl.x += a.x; excl.y += a.y; excl.z += a.z; excl.w += a.w;
                break;
            }
            base_p -= D;
            __syncthreads();   // protect s_D/s_done before warp 0 rewrites them
        }

        // Publish our inclusive prefix (flag 1 -> 2), unless nobody can need it.
        if (!is_last) {
            float4 inc;
            inc.x = excl.x + agg.x; inc.y = excl.y + agg.y;
            inc.z = excl.z + agg.z; inc.w = excl.w + agg.w;
            g_inc[sidx] = inc;
            __threadfence();
            __syncthreads();
            if (tid == 0) st_release_gpu(&g_flags[chain + c], 2u);
        }
    }

    // ---- Epilogue: out = h0 + FACTOR * (exclusive + local_prefix) ----
#pragma unroll
    for (int t = 0; t < TC; t++) {
        float4 o;
        o.x = h.x + FACTOR * (excl.x + v[t].x);
        o.y = h.y + FACTOR * (excl.y + v[t].y);
        o.z = h.z + FACTOR * (excl.z + v[t].z);
        o.w = h.w + FACTOR * (excl.w + v[t].w);
        outv[base + (size_t)t * U4] = o;
    }
}

extern "C" void kernel_launch(void* const* d_in, const int* in_sizes, int n_in,
                              void* d_out, int out_size) {
    (void)in_sizes; (void)n_in; (void)out_size;
    const float4* xv  = (const float4*)d_in[0];   // x:  (16, 4096, 1024) f32
    const float4* h0v = (const float4*)d_in[1];   // h0: (16, 1024) f32
    float4* outv      = (float4*)d_out;           // out:(16, 4096, 1024) f32

    // Reset flags + ticket every launch (captured as a memset node).
    void* flags_ptr = nullptr;
    cudaGetSymbolAddress(&flags_ptr, g_flags);
    cudaMemsetAsync(flags_ptr, 0, (BB * NC + 1) * sizeof(unsigned int), 0);

    rac_scan_kernel<<<BB * NC, THREADS>>>(xv, h0v, outv);
}

// round 5
// speedup vs baseline: 1.2447x; 1.0469x over previous
#include <cuda_runtime.h>
#include <cuda_bf16.h>
#include <cstdint>

// Problem shape
#define BB      16
#define TT      4096
#define UU      1024
#define TC      16                 // t-rows per chunk
#define RR      8                  // rows held in registers
#define SR      8                  // rows held in smem (cp.async, column-private)
#define NC      (TT / TC)          // 256 chunks per batch chain
#define U4      (UU / 4)           // 256 float4 per row
#define THREADS 256                // one thread per float4 column
#define FACTOR  0.5f

// Decoupled-lookback scratch (device globals: no allocation allowed).
__device__ float4 g_agg[BB * NC * U4];          // 16 MiB
__device__ float4 g_inc[BB * NC * U4];          // 16 MiB
// Flags: 0 = invalid, 1 = aggregate ready, 2 = inclusive ready.
// Last slot doubles as the dynamic-ticket counter. Reset by memset each launch.
__device__ unsigned int g_flags[BB * NC + 1];

__device__ __forceinline__ void st_release_gpu(unsigned int* p, unsigned int v) {
    asm volatile("st.release.gpu.u32 [%0], %1;" :: "l"(p), "r"(v) : "memory");
}
__device__ __forceinline__ unsigned int ld_acquire_gpu(const unsigned int* p) {
    unsigned int v;
    asm volatile("ld.acquire.gpu.u32 %0, [%1];" : "=r"(v) : "l"(p) : "memory");
    return v;
}
__device__ __forceinline__ void cp_async16(uint32_t saddr, const void* gaddr) {
    asm volatile("cp.async.cg.shared.global [%0], [%1], 16;" :: "r"(saddr), "l"(gaddr));
}

__global__ __launch_bounds__(THREADS, 3)
void rac_scan_kernel(const float4* __restrict__ xv,
                     const float4* __restrict__ h0v,
                     float4* __restrict__ outv) {
    __shared__ float4 s_tile[SR * THREADS];   // 32 KB, column-private per thread
    __shared__ unsigned int s_vb;
    __shared__ int s_D;
    __shared__ int s_done;

    const int tid = threadIdx.x;

    // Dynamic ticket: chain order == scheduling order (no deadlock).
    if (tid == 0) s_vb = atomicAdd(&g_flags[BB * NC], 1u);
    __syncthreads();
    const unsigned int vb = s_vb;
    const int b = vb & (BB - 1);   // batch fastest -> all 16 chains advance together
    const int c = vb >> 4;         // chunk index along the chain

    const size_t base = ((size_t)b * TT + (size_t)c * TC) * U4 + tid;

    // Rows RR..TC-1 -> smem via cp.async (no register cost, full MLP).
    const uint32_t sbase = (uint32_t)__cvta_generic_to_shared(&s_tile[tid]);
#pragma unroll
    for (int t = 0; t < SR; t++)
        cp_async16(sbase + t * (THREADS * 16),
                   (const void*)(xv + base + (size_t)(RR + t) * U4));
    asm volatile("cp.async.commit_group;" ::: "memory");

    const float4 h = h0v[b * U4 + tid];

    // Rows 0..RR-1 -> registers.
    float4 v[RR];
#pragma unroll
    for (int t = 0; t < RR; t++) v[t] = xv[base + (size_t)t * U4];

    // In-register inclusive prefix over the low 8 rows.
#pragma unroll
    for (int t = 1; t < RR; t++) {
        v[t].x += v[t - 1].x;
        v[t].y += v[t - 1].y;
        v[t].z += v[t - 1].z;
        v[t].w += v[t - 1].w;
    }

    // smem rows are column-private: only this thread's cp.async groups matter.
    asm volatile("cp.async.wait_group 0;" ::: "memory");

    // Local prefix over the high 8 rows, stored back prefixed (local sum only).
    float4 run = make_float4(0.f, 0.f, 0.f, 0.f);
#pragma unroll
    for (int t = 0; t < SR; t++) {
        const float4 a = s_tile[t * THREADS + tid];
        run.x += a.x; run.y += a.y; run.z += a.z; run.w += a.w;
        s_tile[t * THREADS + tid] = run;
    }

    float4 agg;
    agg.x = v[RR - 1].x + run.x;
    agg.y = v[RR - 1].y + run.y;
    agg.z = v[RR - 1].z + run.z;
    agg.w = v[RR - 1].w + run.w;

    const int chain = b * NC;
    const int sidx  = (chain + c) * U4 + tid;
    const bool is_last = (c == NC - 1);
    float4 excl = make_float4(0.f, 0.f, 0.f, 0.f);

    if (c == 0) {
        if (!is_last) {
            g_inc[sidx] = agg;
            __threadfence();
            __syncthreads();
            if (tid == 0) st_release_gpu(&g_flags[chain], 2u);
        }
    } else {
        // Publish aggregate so successors can make progress immediately.
        g_agg[sidx] = agg;
        __threadfence();
        __syncthreads();
        if (tid == 0) st_release_gpu(&g_flags[chain + c], 1u);

        // Windowed lookback: warp 0 polls 32 predecessor flags at once.
        int base_p = c - 1;
        for (;;) {
            if (tid < 32) {
                const int p = base_p - tid;
                const unsigned f = (p >= 0) ? ld_acquire_gpu(&g_flags[chain + p]) : 0u;
                const unsigned b1 = __ballot_sync(0xffffffffu, f >= 1u);
                const unsigned b2 = __ballot_sync(0xffffffffu, f == 2u);
                if (tid == 0) {
                    const int k = __ffs(~b1);                 // first not-ready lane (+1); 0 => all ready
                    const int nready = (k == 0) ? 32 : (k - 1);
                    const int l2 = __ffs(b2) - 1;             // nearest inclusive; -1 if none
                    if (l2 >= 0 && l2 <= nready) { s_done = 1; s_D = l2; }
                    else                         { s_done = 0; s_D = nready; }
                }
            }
            __syncthreads();
            const int D = s_D;
            const int done = s_done;
            for (int l = 0; l < D; l++) {
                const float4 a = __ldcg(&g_agg[(chain + base_p - l) * U4 + tid]);
                excl.x += a.x; excl.y += a.y; excl.z += a.z; excl.w += a.w;
            }
            if (done) {
                const float4 a = __ldcg(&g_inc[(chain + base_p - D) * U4 + tid]);
                excl.x += a.x; excl.y += a.y; excl.z += a.z; excl.w += a.w;
                break;
            }
            base_p -= D;
            __syncthreads();   // protect s_D/s_done before next poll round
        }

        // Publish our inclusive prefix (flag 1 -> 2), unless nobody needs it.
        if (!is_last) {
            float4 inc;
            inc.x = excl.x + agg.x; inc.y = excl.y + agg.y;
            inc.z = excl.z + agg.z; inc.w = excl.w + agg.w;
            g_inc[sidx] = inc;
            __threadfence();
            __syncthreads();
            if (tid == 0) st_release_gpu(&g_flags[chain + c], 2u);
        }
    }

    // ---- Epilogue: out = h0 + FACTOR * (exclusive + local_prefix) ----
#pragma unroll
    for (int t = 0; t < RR; t++) {
        float4 o;
        o.x = h.x + FACTOR * (excl.x + v[t].x);
        o.y = h.y + FACTOR * (excl.y + v[t].y);
        o.z = h.z + FACTOR * (excl.z + v[t].z);
        o.w = h.w + FACTOR * (excl.w + v[t].w);
        outv[base + (size_t)t * U4] = o;
    }
    const float4 lo = v[RR - 1];
#pragma unroll
    for (int t = 0; t < SR; t++) {
        const float4 p = s_tile[t * THREADS + tid];
        float4 o;
        o.x = h.x + FACTOR * (excl.x + lo.x + p.x);
        o.y = h.y + FACTOR * (excl.y + lo.y + p.y);
        o.z = h.z + FACTOR * (excl.z + lo.z + p.z);
        o.w = h.w + FACTOR * (excl.w + lo.w + p.w);
        outv[base + (size_t)(RR + t) * U4] = o;
    }
}

extern "C" void kernel_launch(void* const* d_in, const int* in_sizes, int n_in,
                              void* d_out, int out_size) {
    (void)in_sizes; (void)n_in; (void)out_size;
    const float4* xv  = (const float4*)d_in[0];   // x:  (16, 4096, 1024) f32
    const float4* h0v = (const float4*)d_in[1];   // h0: (16, 1024) f32
    float4* outv      = (float4*)d_out;           // out:(16, 4096, 1024) f32

    // Reset flags + ticket every launch (captured as a memset node).
    void* flags_ptr = nullptr;
    cudaGetSymbolAddress(&flags_ptr, g_flags);
    cudaMemsetAsync(flags_ptr, 0, (BB * NC + 1) * sizeof(unsigned int), 0);

    rac_scan_kernel<<<BB * NC, THREADS>>>(xv, h0v, outv);
}

// round 6
// speedup vs baseline: 1.2955x; 1.0408x over previous
#include <cuda_runtime.h>
#include <cstdint>

// Problem shape
#define BB      16
#define TT      4096
#define UU      1024
#define TC      16                 // t-rows per chunk
#define RR      4                  // rows held in registers
#define SR      12                 // rows via cp.async into smem (column-private)
#define NC      (TT / TC)          // 256 chunks per batch chain
#define U4      (UU / 4)           // 256 float4 per row
#define THREADS 256                // one thread per float4 column
#define FACTOR  0.5f

// Decoupled-lookback scratch (device globals: no allocation allowed).
__device__ float4 g_agg[BB * NC * U4];          // 16 MiB
__device__ float4 g_inc[BB * NC * U4];          // 16 MiB
// Flags: 0 = invalid, 1 = aggregate ready, 2 = inclusive ready.
// Last slot doubles as the dynamic-ticket counter. Reset by memset each launch.
__device__ unsigned int g_flags[BB * NC + 1];

__device__ __forceinline__ void st_release_gpu(unsigned int* p, unsigned int v) {
    asm volatile("st.release.gpu.u32 [%0], %1;" :: "l"(p), "r"(v) : "memory");
}
__device__ __forceinline__ unsigned int ld_acquire_gpu(const unsigned int* p) {
    unsigned int v;
    asm volatile("ld.acquire.gpu.u32 %0, [%1];" : "=r"(v) : "l"(p) : "memory");
    return v;
}
__device__ __forceinline__ void cp_async16(uint32_t saddr, const void* gaddr) {
    asm volatile("cp.async.cg.shared.global [%0], [%1], 16;" :: "r"(saddr), "l"(gaddr));
}

__global__ __launch_bounds__(THREADS, 4)
void rac_scan_kernel(const float4* __restrict__ xv,
                     const float4* __restrict__ h0v,
                     float4* __restrict__ outv) {
    __shared__ float4 s_tile[SR * THREADS];   // 48 KB, column-private per thread
    __shared__ unsigned int s_vb;
    __shared__ int s_D;
    __shared__ int s_done;

    const int tid = threadIdx.x;

    // Dynamic ticket: chain order == scheduling order (no deadlock).
    if (tid == 0) s_vb = atomicAdd(&g_flags[BB * NC], 1u);
    __syncthreads();
    const unsigned int vb = s_vb;
    const int b = vb & (BB - 1);   // batch fastest -> all 16 chains advance together
    const int c = vb >> 4;         // chunk index along the chain

    const size_t base = ((size_t)b * TT + (size_t)c * TC) * U4 + tid;

    // Rows RR..TC-1 -> smem via cp.async (no register cost, deep MLP).
    const uint32_t sbase = (uint32_t)__cvta_generic_to_shared(&s_tile[tid]);
#pragma unroll
    for (int t = 0; t < SR; t++)
        cp_async16(sbase + t * (THREADS * 16),
                   (const void*)(xv + base + (size_t)(RR + t) * U4));
    asm volatile("cp.async.commit_group;" ::: "memory");

    const float4 h = h0v[b * U4 + tid];

    // Rows 0..RR-1 -> registers, prefixed.
    float4 v[RR];
#pragma unroll
    for (int t = 0; t < RR; t++) v[t] = xv[base + (size_t)t * U4];
#pragma unroll
    for (int t = 1; t < RR; t++) {
        v[t].x += v[t - 1].x;
        v[t].y += v[t - 1].y;
        v[t].z += v[t - 1].z;
        v[t].w += v[t - 1].w;
    }

    const int chain = b * NC;
    const int sidx  = (chain + c) * U4 + tid;
    const bool is_last = (c == NC - 1);
    float4 excl = make_float4(0.f, 0.f, 0.f, 0.f);

    // ---- Pre-phase lookback: overlapped with the cp.async flight. ----
    // Consume whatever predecessors have already published; NEVER blocks:
    // breaks as soon as a poll round shows no progress.
    int base_p = c - 1;
    bool done = (c == 0);
    while (!done) {
        if (tid < 32) {
            const int p = base_p - tid;
            const unsigned f = (p >= 0) ? ld_acquire_gpu(&g_flags[chain + p]) : 0u;
            const unsigned b1 = __ballot_sync(0xffffffffu, f >= 1u);
            const unsigned b2 = __ballot_sync(0xffffffffu, f == 2u);
            if (tid == 0) {
                const int k = __ffs(~b1);                 // first not-ready lane (+1); 0 => all ready
                const int nready = (k == 0) ? 32 : (k - 1);
                const int l2 = __ffs(b2) - 1;             // nearest inclusive; -1 if none
                if (l2 >= 0 && l2 <= nready) { s_done = 1; s_D = l2; }
                else                         { s_done = 0; s_D = nready; }
            }
        }
        __syncthreads();
        const int D = s_D;
        const int fin = s_done;
        if (!fin && D == 0) break;       // no progress yet -> go back to our load
        for (int l = 0; l < D; l++) {
            const float4 a = __ldcg(&g_agg[(chain + base_p - l) * U4 + tid]);
            excl.x += a.x; excl.y += a.y; excl.z += a.z; excl.w += a.w;
        }
        if (fin) {
            const float4 a = __ldcg(&g_inc[(chain + base_p - D) * U4 + tid]);
            excl.x += a.x; excl.y += a.y; excl.z += a.z; excl.w += a.w;
            done = true;
            break;
        }
        base_p -= D;
        __syncthreads();                 // protect s_D/s_done before next poll
    }

    // ---- Wait for data; local prefix over smem rows (column-private, no sync). ----
    asm volatile("cp.async.wait_group 0;" ::: "memory");
    float4 run = make_float4(0.f, 0.f, 0.f, 0.f);
#pragma unroll
    for (int t = 0; t < SR; t++) {
        const float4 a = s_tile[t * THREADS + tid];
        run.x += a.x; run.y += a.y; run.z += a.z; run.w += a.w;
        s_tile[t * THREADS + tid] = run;
    }
    float4 agg;
    agg.x = v[RR - 1].x + run.x;
    agg.y = v[RR - 1].y + run.y;
    agg.z = v[RR - 1].z + run.z;
    agg.w = v[RR - 1].w + run.w;

    if (done) {
        // Lookback resolved during the load: single publish, inclusive directly.
        if (!is_last) {
            float4 inc;
            inc.x = excl.x + agg.x; inc.y = excl.y + agg.y;
            inc.z = excl.z + agg.z; inc.w = excl.w + agg.w;
            g_inc[sidx] = inc;
            __syncthreads();             // all data stores happen-before the release
            if (tid == 0) st_release_gpu(&g_flags[chain + c], 2u);
        }
    } else {
        // Publish aggregate so successors can make progress immediately.
        g_agg[sidx] = agg;
        __syncthreads();                 // HB for all threads' stores; also protects s_D
        if (tid == 0) st_release_gpu(&g_flags[chain + c], 1u);

        // ---- Residual lookback (blocking, same windowed protocol). ----
        for (;;) {
            if (tid < 32) {
                const int p = base_p - tid;
                const unsigned f = (p >= 0) ? ld_acquire_gpu(&g_flags[chain + p]) : 0u;
                const unsigned b1 = __ballot_sync(0xffffffffu, f >= 1u);
                const unsigned b2 = __ballot_sync(0xffffffffu, f == 2u);
                if (tid == 0) {
                    const int k = __ffs(~b1);
                    const int nready = (k == 0) ? 32 : (k - 1);
                    const int l2 = __ffs(b2) - 1;
                    if (l2 >= 0 && l2 <= nready) { s_done = 1; s_D = l2; }
                    else                         { s_done = 0; s_D = nready; }
                }
            }
            __syncthreads();
            const int D = s_D;
            const int fin = s_done;
            for (int l = 0; l < D; l++) {
                const float4 a = __ldcg(&g_agg[(chain + base_p - l) * U4 + tid]);
                excl.x += a.x; excl.y += a.y; excl.z += a.z; excl.w += a.w;
            }
            if (fin) {
                const float4 a = __ldcg(&g_inc[(chain + base_p - D) * U4 + tid]);
                excl.x += a.x; excl.y += a.y; excl.z += a.z; excl.w += a.w;
                break;
            }
            base_p -= D;
            __syncthreads();
        }

        // Upgrade to inclusive (flag 1 -> 2).
        if (!is_last) {
            float4 inc;
            inc.x = excl.x + agg.x; inc.y = excl.y + agg.y;
            inc.z = excl.z + agg.z; inc.w = excl.w + agg.w;
            g_inc[sidx] = inc;
            __syncthreads();
            if (tid == 0) st_release_gpu(&g_flags[chain + c], 2u);
        }
    }

    // ---- Epilogue: out = h0 + FACTOR * (exclusive + local_prefix) ----
#pragma unroll
    for (int t = 0; t < RR; t++) {
        float4 o;
        o.x = h.x + FACTOR * (excl.x + v[t].x);
        o.y = h.y + FACTOR * (excl.y + v[t].y);
        o.z = h.z + FACTOR * (excl.z + v[t].z);
        o.w = h.w + FACTOR * (excl.w + v[t].w);
        outv[base + (size_t)t * U4] = o;
    }
    const float4 lo = v[RR - 1];
#pragma unroll
    for (int t = 0; t < SR; t++) {
        const float4 p = s_tile[t * THREADS + tid];
        float4 o;
        o.x = h.x + FACTOR * (excl.x + lo.x + p.x);
        o.y = h.y + FACTOR * (excl.y + lo.y + p.y);
        o.z = h.z + FACTOR * (excl.z + lo.z + p.z);
        o.w = h.w + FACTOR * (excl.w + lo.w + p.w);
        outv[base + (size_t)(RR + t) * U4] = o;
    }
}

extern "C" void kernel_launch(void* const* d_in, const int* in_sizes, int n_in,
                              void* d_out, int out_size) {
    (void)in_sizes; (void)n_in; (void)out_size;
    const float4* xv  = (const float4*)d_in[0];   // x:  (16, 4096, 1024) f32
    const float4* h0v = (const float4*)d_in[1];   // h0: (16, 1024) f32
    float4* outv      = (float4*)d_out;           // out:(16, 4096, 1024) f32

    // Reset flags + ticket every launch (captured as a memset node).
    void* flags_ptr = nullptr;
    cudaGetSymbolAddress(&flags_ptr, g_flags);
    cudaMemsetAsync(flags_ptr, 0, (BB * NC + 1) * sizeof(unsigned int), 0);

    rac_scan_kernel<<<BB * NC, THREADS>>>(xv, h0v, outv);
}